// round 15
// baseline (speedup 1.0000x reference)
#include <cuda_runtime.h>
#include <cuda_bf16.h>
#include <cuda_fp16.h>
#include <cstdint>

// Problem constants (dataset-fixed): N=100000, E=1600000, F=128, H=4, C=32
#define NMAX 100000
#define EMAX 1600000

// Scratch (device globals — allocation-free per harness rules)
__device__ __align__(16) __half g_hf[(size_t)NMAX * 128];  // 25.6 MB, fp16 h
__device__ __align__(16) float g_asrc[(size_t)NMAX * 4];
__device__ __align__(16) float g_adst[(size_t)NMAX * 4];
__device__ __align__(16) __nv_bfloat16 g_wtb_hi[128 * 128];
__device__ __align__(16) __nv_bfloat16 g_wtb_lo[128 * 128];
__device__ int g_deg[NMAX + 1];
__device__ int g_off[NMAX + 1];
__device__ int g_cur[NMAX];
__device__ int g_csrc[EMAX];
__device__ int g_bsum[256];
__device__ int g_bpre[256];
__device__ int g_is64;

__device__ __forceinline__ float sel4(float4 v, int h) {
    float a = (h & 1) ? v.y : v.x;
    float b = (h & 1) ? v.w : v.z;
    return (h & 2) ? b : a;
}
__device__ __forceinline__ float lrelu(float v) { return v > 0.f ? v : 0.2f * v; }
__device__ __forceinline__ float bf16r(float x) {
    return __bfloat162float(__float2bfloat16(x));
}
__device__ __forceinline__ uint32_t pack_bf2(float lo, float hi) {
    uint32_t r;
    asm("cvt.rn.bf16x2.f32 %0, %1, %2;" : "=r"(r) : "f"(hi), "f"(lo));
    return r;
}
__device__ __forceinline__ void mma_bf16(float* c, uint32_t a0, uint32_t a1,
                                         uint32_t a2, uint32_t a3,
                                         uint32_t b0, uint32_t b1) {
    asm volatile(
        "mma.sync.aligned.m16n8k16.row.col.f32.bf16.bf16.f32 "
        "{%0,%1,%2,%3}, {%4,%5,%6,%7}, {%8,%9}, {%0,%1,%2,%3};"
        : "+f"(c[0]), "+f"(c[1]), "+f"(c[2]), "+f"(c[3])
        : "r"(a0), "r"(a1), "r"(a2), "r"(a3), "r"(b0), "r"(b1));
}
__device__ __forceinline__ void ldsm_x4(uint32_t* r, uint32_t saddr) {
    asm volatile(
        "ldmatrix.sync.aligned.m8n8.x4.shared.b16 {%0,%1,%2,%3}, [%4];"
        : "=r"(r[0]), "=r"(r[1]), "=r"(r[2]), "=r"(r[3]) : "r"(saddr));
}

// ---------------------------------------------------------------------------
__global__ void k_detect(const void* ei, int N) {
    const long long* p = (const long long*)ei;
    bool ok64 = true;
#pragma unroll
    for (int i = 0; i < 8; i++) {
        long long v = p[i];
        if (v < 0 || v >= N) ok64 = false;
    }
    g_is64 = ok64 ? 1 : 0;
}
__device__ __forceinline__ int edge_src(const void* ei, int e) {
    return g_is64 ? (int)__ldg((const long long*)ei + e) : __ldg((const int*)ei + e);
}
__device__ __forceinline__ int edge_dst(const void* ei, int e, int E) {
    return g_is64 ? (int)__ldg((const long long*)ei + (size_t)E + e)
                  : __ldg((const int*)ei + (size_t)E + e);
}

// ---------------------------------------------------------------------------
// CSR build
// ---------------------------------------------------------------------------
__global__ void k_zero(int N) {
    int i = blockIdx.x * blockDim.x + threadIdx.x;
    if (i <= N) g_deg[i] = 0;
}
__global__ void k_hist(const void* __restrict__ ei, int E) {
    int e = blockIdx.x * blockDim.x + threadIdx.x;
    if (e < E) atomicAdd(&g_deg[edge_dst(ei, e, E)], 1);
}
__global__ void __launch_bounds__(1024) k_scan1(int n) {
    __shared__ int warp_sums[32];
    const int tid = threadIdx.x, lane = tid & 31, wid = tid >> 5;
    int i = blockIdx.x * 1024 + tid;
    int v = (i < n) ? g_deg[i] : 0;
    int x = v;
#pragma unroll
    for (int off = 1; off < 32; off <<= 1) {
        int y = __shfl_up_sync(0xFFFFFFFFu, x, off);
        if (lane >= off) x += y;
    }
    if (lane == 31) warp_sums[wid] = x;
    __syncthreads();
    if (wid == 0) {
        int s = warp_sums[lane];
#pragma unroll
        for (int off = 1; off < 32; off <<= 1) {
            int y = __shfl_up_sync(0xFFFFFFFFu, s, off);
            if (lane >= off) s += y;
        }
        warp_sums[lane] = s;
    }
    __syncthreads();
    int incl = x + (wid ? warp_sums[wid - 1] : 0);
    if (i < n) g_off[i] = incl - v;
    if (tid == 1023) g_bsum[blockIdx.x] = incl;
}
__global__ void __launch_bounds__(256) k_scan2(int nb) {
    __shared__ int s[256];
    int tid = threadIdx.x;
    s[tid] = (tid < nb) ? g_bsum[tid] : 0;
    __syncthreads();
#pragma unroll
    for (int off = 1; off < 256; off <<= 1) {
        int v = (tid >= off) ? s[tid - off] : 0;
        __syncthreads();
        s[tid] += v;
        __syncthreads();
    }
    if (tid < nb) g_bpre[tid] = s[tid] - g_bsum[tid];
}
__global__ void __launch_bounds__(1024) k_scan3(int n, int E) {
    int i = blockIdx.x * 1024 + threadIdx.x;
    if (i < n) {
        int v = g_off[i] + g_bpre[blockIdx.x];
        g_off[i] = v;
        g_cur[i] = v;
    }
    if (i == n) g_off[n] = E;
}
__global__ void k_csr(const void* __restrict__ ei, int E) {
    int e = blockIdx.x * blockDim.x + threadIdx.x;
    if (e >= E) return;
    int s = edge_src(ei, e);
    int d = edge_dst(ei, e, E);
    int pos = atomicAdd(&g_cur[d], 1);
    g_csrc[pos] = s;
}

// ---------------------------------------------------------------------------
// W^T bf16 split precompute
// ---------------------------------------------------------------------------
__global__ void k_wt(const float* __restrict__ W) {
    int i = blockIdx.x * blockDim.x + threadIdx.x;
    if (i >= 128 * 128) return;
    int n = i >> 7, k = i & 127;
    float v = __ldg(W + k * 128 + n);
    float hi = bf16r(v);
    g_wtb_hi[i] = __float2bfloat16(v);
    g_wtb_lo[i] = __float2bfloat16(v - hi);
}

// ---------------------------------------------------------------------------
// GEMM via mma.sync m16n8k16 bf16, 3-term split + fused logits.
// 128x128 CTA tile, 512 threads / 16 warps (warp tile 32m x 32n), ldmatrix.
// (unchanged from R14)
// ---------------------------------------------------------------------------
#define AS_STRIDE 136
#define SM_AHI 0
#define SM_ALO (128 * AS_STRIDE * 2)
#define SM_BHI (SM_ALO + 128 * AS_STRIDE * 2)
#define SM_BLO (SM_BHI + 128 * AS_STRIDE * 2)
#define SM_ATT (SM_BLO + 128 * AS_STRIDE * 2)
#define SM_TOT (SM_ATT + 1024)

__global__ void __launch_bounds__(512, 1)
k_gemm_mma(const float* __restrict__ x,
           const float* __restrict__ att_src, const float* __restrict__ att_dst,
           int N) {
    extern __shared__ char smem[];
    const int tid = threadIdx.x;
    const int row0 = blockIdx.x * 128;

    if (tid < 128)       *(float*)(smem + SM_ATT + tid * 4) = att_src[tid];
    else if (tid < 256)  *(float*)(smem + SM_ATT + 512 + (tid - 128) * 4) = att_dst[tid - 128];

    const float4* Xg = (const float4*)x;
#pragma unroll
    for (int i = 0; i < 8; i++) {
        int idx = tid + i * 512;
        int m = idx >> 5, kf4 = idx & 31;
        int gr = row0 + m;
        float4 v = (gr < N) ? Xg[(size_t)gr * 32 + kf4]
                            : make_float4(0.f, 0.f, 0.f, 0.f);
        float hx = bf16r(v.x), hy = bf16r(v.y), hz = bf16r(v.z), hw = bf16r(v.w);
        uint2 hi2 = make_uint2(pack_bf2(hx, hy), pack_bf2(hz, hw));
        uint2 lo2 = make_uint2(pack_bf2(v.x - hx, v.y - hy),
                               pack_bf2(v.z - hz, v.w - hw));
        uint32_t off = (uint32_t)(m * AS_STRIDE + kf4 * 4) * 2;
        *(uint2*)(smem + SM_AHI + off) = hi2;
        *(uint2*)(smem + SM_ALO + off) = lo2;
    }
#pragma unroll
    for (int i = 0; i < 4; i++) {
        int idx = tid + i * 512;
        int n = idx >> 4, kb = (idx & 15) * 8;
        uint32_t off = (uint32_t)(n * AS_STRIDE + kb) * 2;
        *(uint4*)(smem + SM_BHI + off) = *(const uint4*)(g_wtb_hi + n * 128 + kb);
        *(uint4*)(smem + SM_BLO + off) = *(const uint4*)(g_wtb_lo + n * 128 + kb);
    }
    __syncthreads();

    const int w = tid >> 5, lane = tid & 31;
    const int mw = w & 3, nw = w >> 2;
    const int m0 = mw * 32, n0 = nw * 32;
    const int g = lane >> 2, q = lane & 3;

    float acc[2][4][4];
#pragma unroll
    for (int a = 0; a < 2; a++)
#pragma unroll
        for (int b = 0; b < 4; b++)
#pragma unroll
            for (int c = 0; c < 4; c++) acc[a][b][c] = 0.f;

    const uint32_t sb = (uint32_t)__cvta_generic_to_shared(smem);
    uint32_t aHi[2], aLo[2], bHi[2], bLo[2];
    {
        int rl = ((lane >> 3) & 1) * 8 + (lane & 7);
        int kk = (lane >> 4) * 8;
#pragma unroll
        for (int ma = 0; ma < 2; ma++) {
            uint32_t off = (uint32_t)((m0 + ma * 16 + rl) * AS_STRIDE + kk) * 2;
            aHi[ma] = sb + SM_AHI + off;
            aLo[ma] = sb + SM_ALO + off;
        }
        int rlb = (lane >> 4) * 8 + (lane & 7);
        int kkb = ((lane >> 3) & 1) * 8;
#pragma unroll
        for (int p = 0; p < 2; p++) {
            uint32_t off = (uint32_t)((n0 + p * 16 + rlb) * AS_STRIDE + kkb) * 2;
            bHi[p] = sb + SM_BHI + off;
            bLo[p] = sb + SM_BLO + off;
        }
    }

#pragma unroll
    for (int ka = 0; ka < 8; ka++) {
        const uint32_t koff = ka * 32;
        uint32_t ah[2][4], al[2][4];
        uint32_t bh[4][2], bl[4][2];
#pragma unroll
        for (int ma = 0; ma < 2; ma++) {
            ldsm_x4(ah[ma], aHi[ma] + koff);
            ldsm_x4(al[ma], aLo[ma] + koff);
        }
#pragma unroll
        for (int p = 0; p < 2; p++) {
            ldsm_x4(&bh[2 * p][0], bHi[p] + koff);
            ldsm_x4(&bl[2 * p][0], bLo[p] + koff);
        }
#pragma unroll
        for (int ma = 0; ma < 2; ma++)
#pragma unroll
            for (int na = 0; na < 4; na++) {
                mma_bf16(acc[ma][na], ah[ma][0], ah[ma][1], ah[ma][2], ah[ma][3],
                         bh[na][0], bh[na][1]);
                mma_bf16(acc[ma][na], ah[ma][0], ah[ma][1], ah[ma][2], ah[ma][3],
                         bl[na][0], bl[na][1]);
                mma_bf16(acc[ma][na], al[ma][0], al[ma][1], al[ma][2], al[ma][3],
                         bh[na][0], bh[na][1]);
            }
    }

    const float* s_as = (const float*)(smem + SM_ATT);
    const float* s_ad = (const float*)(smem + SM_ATT + 512);

#pragma unroll
    for (int ma = 0; ma < 2; ma++) {
#pragma unroll
        for (int half = 0; half < 2; half++) {
            int row = row0 + m0 + ma * 16 + g + half * 8;
            float as0 = 0.f, ad0 = 0.f;
#pragma unroll
            for (int na = 0; na < 4; na++) {
                int col = n0 + na * 8 + q * 2;
                float v0 = acc[ma][na][half * 2];
                float v1 = acc[ma][na][half * 2 + 1];
                if (row < N)
                    *(__half2*)(g_hf + (size_t)row * 128 + col) =
                        __floats2half2_rn(v0, v1);
                as0 += v0 * s_as[col] + v1 * s_as[col + 1];
                ad0 += v0 * s_ad[col] + v1 * s_ad[col + 1];
            }
#pragma unroll
            for (int off = 1; off < 4; off <<= 1) {
                as0 += __shfl_xor_sync(0xFFFFFFFFu, as0, off);
                ad0 += __shfl_xor_sync(0xFFFFFFFFu, ad0, off);
            }
            if (q == 0 && row < N) {
                g_asrc[(size_t)row * 4 + nw] = as0;
                g_adst[(size_t)row * 4 + nw] = ad0;
            }
        }
    }
}

// ---------------------------------------------------------------------------
// Aggregation v5: TWO nodes per warp with interleaved Phase B gathers.
// Same per-lane layout as v3 (uint2/lane), doubled independent loads in
// flight (MLP ~8). Each node keeps its own acc/den/output. Zero atomics.
// ---------------------------------------------------------------------------
__global__ void __launch_bounds__(256) k_agg(float* __restrict__ out,
                                             const float* __restrict__ bias,
                                             int N) {
    __shared__ float p_sm[8][2][4][32];
    __shared__ int   s_sm[8][2][32];
    const int wib = threadIdx.x >> 5;
    const int wp = (blockIdx.x * blockDim.x + threadIdx.x) >> 5;
    const int lane = threadIdx.x & 31;
    const int d0 = wp * 2;
    if (d0 >= N) return;
    const int d1 = d0 + 1;
    const bool has1 = d1 < N;
    const int hh = lane >> 3;

    const float4 ad40 = *(const float4*)(g_adst + (size_t)d0 * 4);
    const float4 ad41 = has1 ? *(const float4*)(g_adst + (size_t)d1 * 4)
                             : make_float4(0.f, 0.f, 0.f, 0.f);
    const float adh0 = sel4(ad40, hh);
    const float adh1 = sel4(ad41, hh);

    const int beg0 = g_off[d0], end0 = g_off[d0 + 1];
    const int beg1 = has1 ? g_off[d1] : 0;
    const int end1 = has1 ? g_off[d1 + 1] : 0;

    // self loops seed accumulators (independent chains)
    float den0 = __expf(lrelu(__ldg(&g_asrc[(size_t)d0 * 4 + hh]) + adh0));
    float den1 = 0.f;
    float4 acc0, acc1 = make_float4(0.f, 0.f, 0.f, 0.f);
    {
        uint2 u = __ldg((const uint2*)(g_hf + (size_t)d0 * 128) + lane);
        float2 f0 = __half22float2(*(__half2*)&u.x);
        float2 f1 = __half22float2(*(__half2*)&u.y);
        acc0 = make_float4(den0 * f0.x, den0 * f0.y, den0 * f1.x, den0 * f1.y);
    }
    if (has1) {
        den1 = __expf(lrelu(__ldg(&g_asrc[(size_t)d1 * 4 + hh]) + adh1));
        uint2 u = __ldg((const uint2*)(g_hf + (size_t)d1 * 128) + lane);
        float2 f0 = __half22float2(*(__half2*)&u.x);
        float2 f1 = __half22float2(*(__half2*)&u.y);
        acc1 = make_float4(den1 * f0.x, den1 * f0.y, den1 * f1.x, den1 * f1.y);
    }

    for (int base0 = beg0, base1 = beg1;
         base0 < end0 || base1 < end1;
         base0 += 32, base1 += 32) {
        const int cnt0 = max(0, min(32, end0 - base0));
        const int cnt1 = max(0, min(32, end1 - base1));
        // Phase A: both nodes' chunks in parallel (independent chains)
        {
            int j0 = base0 + lane;
            int j1 = base1 + lane;
            int s0 = 0, s1 = 0;
            bool v0 = (j0 < end0), v1 = (j1 < end1);
            if (v0) s0 = __ldg(&g_csrc[j0]);
            if (v1) s1 = __ldg(&g_csrc[j1]);
            float4 p0 = make_float4(0.f, 0.f, 0.f, 0.f);
            float4 p1 = make_float4(0.f, 0.f, 0.f, 0.f);
            if (v0) {
                float4 a4 = *(const float4*)(g_asrc + (size_t)s0 * 4);
                p0.x = __expf(lrelu(a4.x + ad40.x));
                p0.y = __expf(lrelu(a4.y + ad40.y));
                p0.z = __expf(lrelu(a4.z + ad40.z));
                p0.w = __expf(lrelu(a4.w + ad40.w));
            }
            if (v1) {
                float4 a4 = *(const float4*)(g_asrc + (size_t)s1 * 4);
                p1.x = __expf(lrelu(a4.x + ad41.x));
                p1.y = __expf(lrelu(a4.y + ad41.y));
                p1.z = __expf(lrelu(a4.z + ad41.z));
                p1.w = __expf(lrelu(a4.w + ad41.w));
            }
            s_sm[wib][0][lane] = s0;
            s_sm[wib][1][lane] = s1;
            p_sm[wib][0][0][lane] = p0.x; p_sm[wib][0][1][lane] = p0.y;
            p_sm[wib][0][2][lane] = p0.z; p_sm[wib][0][3][lane] = p0.w;
            p_sm[wib][1][0][lane] = p1.x; p_sm[wib][1][1][lane] = p1.y;
            p_sm[wib][1][2][lane] = p1.z; p_sm[wib][1][3][lane] = p1.w;
        }
        __syncwarp();
        // Phase B: interleave the two nodes' edge gathers (all independent)
        const int cmax = max(cnt0, cnt1);
#pragma unroll 4
        for (int t = 0; t < cmax; t++) {
            if (t < cnt0) {
                int ss = s_sm[wib][0][t];
                float p = p_sm[wib][0][hh][t];
                den0 += p;
                uint2 u = __ldg((const uint2*)(g_hf + (size_t)ss * 128) + lane);
                float2 f0 = __half22float2(*(__half2*)&u.x);
                float2 f1 = __half22float2(*(__half2*)&u.y);
                acc0.x = fmaf(p, f0.x, acc0.x);
                acc0.y = fmaf(p, f0.y, acc0.y);
                acc0.z = fmaf(p, f1.x, acc0.z);
                acc0.w = fmaf(p, f1.y, acc0.w);
            }
            if (t < cnt1) {
                int ss = s_sm[wib][1][t];
                float p = p_sm[wib][1][hh][t];
                den1 += p;
                uint2 u = __ldg((const uint2*)(g_hf + (size_t)ss * 128) + lane);
                float2 f0 = __half22float2(*(__half2*)&u.x);
                float2 f1 = __half22float2(*(__half2*)&u.y);
                acc1.x = fmaf(p, f0.x, acc1.x);
                acc1.y = fmaf(p, f0.y, acc1.y);
                acc1.z = fmaf(p, f1.x, acc1.z);
                acc1.w = fmaf(p, f1.y, acc1.w);
            }
        }
        __syncwarp();
    }

    const float4 b4 = ((const float4*)bias)[lane];
    {
        const float inv = __fdividef(1.0f, den0);
        float4 o;
        o.x = fmaf(acc0.x, inv, b4.x);
        o.y = fmaf(acc0.y, inv, b4.y);
        o.z = fmaf(acc0.z, inv, b4.z);
        o.w = fmaf(acc0.w, inv, b4.w);
        ((float4*)(out + (size_t)d0 * 128))[lane] = o;
    }
    if (has1) {
        const float inv = __fdividef(1.0f, den1);
        float4 o;
        o.x = fmaf(acc1.x, inv, b4.x);
        o.y = fmaf(acc1.y, inv, b4.y);
        o.z = fmaf(acc1.z, inv, b4.z);
        o.w = fmaf(acc1.w, inv, b4.w);
        ((float4*)(out + (size_t)d1 * 128))[lane] = o;
    }
}

// ---------------------------------------------------------------------------
extern "C" void kernel_launch(void* const* d_in, const int* in_sizes, int n_in,
                              void* d_out, int out_size) {
    int idx_W = -1;
    int small[3] = {-1, -1, -1}; int ns = 0;
    for (int i = 0; i < n_in; i++) {
        int sz = in_sizes[i];
        if (sz == 128 && ns < 3)  small[ns++] = i;
        else if (sz == 128 * 128) idx_W = i;
    }
    int idx_x = -1, idx_e = -1;
    for (int i = 0; i < n_in; i++) {
        if (in_sizes[i] == 128 || in_sizes[i] == 128 * 128) continue;
        if (idx_x < 0 || in_sizes[i] > in_sizes[idx_x]) { idx_e = idx_x; idx_x = i; }
        else if (idx_e < 0 || in_sizes[i] > in_sizes[idx_e]) { idx_e = i; }
    }
    int idx_asrc, idx_adst, idx_bias;
    if (idx_x < small[0]) { idx_asrc = small[0]; idx_adst = small[1]; idx_bias = small[2]; }
    else                  { idx_adst = small[0]; idx_asrc = small[1]; idx_bias = small[2]; }

    const float* x       = (const float*)d_in[idx_x];
    const void*  ei      = d_in[idx_e];
    const float* W       = (const float*)d_in[idx_W];
    const float* att_src = (const float*)d_in[idx_asrc];
    const float* att_dst = (const float*)d_in[idx_adst];
    const float* bias    = (const float*)d_in[idx_bias];
    float* out           = (float*)d_out;

    const int N = in_sizes[idx_x] / 128;
    const int E = in_sizes[idx_e] / 2;
    const int nb = (N + 1023) / 1024;

    static cudaStream_t s2 = nullptr;
    static cudaEvent_t evFork = nullptr, evJoin = nullptr;
    if (!s2) {
        cudaFuncSetAttribute(k_gemm_mma, cudaFuncAttributeMaxDynamicSharedMemorySize, SM_TOT);
        cudaStreamCreateWithFlags(&s2, cudaStreamNonBlocking);
        cudaEventCreateWithFlags(&evFork, cudaEventDisableTiming);
        cudaEventCreateWithFlags(&evJoin, cudaEventDisableTiming);
    }

    cudaEventRecord(evFork, 0);
    cudaStreamWaitEvent(s2, evFork, 0);

    // Submission order: index 3 = k_gemm_mma (ncu profiles 4th launch).
    k_detect<<<1, 1, 0, s2>>>(ei, N);                            // 0
    k_wt<<<(128 * 128 + 255) / 256, 256>>>(W);                   // 1 (default)
    k_zero<<<(N + 256) / 256, 256, 0, s2>>>(N);                  // 2
    k_gemm_mma<<<(N + 127) / 128, 512, SM_TOT>>>(x, att_src, att_dst, N); // 3 (default)
    k_hist<<<(E + 255) / 256, 256, 0, s2>>>(ei, E);              // 4
    k_scan1<<<nb, 1024, 0, s2>>>(N);
    k_scan2<<<1, 256, 0, s2>>>(nb);
    k_scan3<<<nb + 1, 1024, 0, s2>>>(N, E);
    k_csr<<<(E + 255) / 256, 256, 0, s2>>>(ei, E);

    cudaEventRecord(evJoin, s2);
    cudaStreamWaitEvent(0, evJoin, 0);
    {
        int pairs = (N + 1) / 2;
        long long threads = (long long)pairs * 32;
        int blocks = (int)((threads + 255) / 256);
        k_agg<<<blocks, 256>>>(out, bias, N);
    }
}

// round 16
// speedup vs baseline: 1.2301x; 1.2301x over previous
#include <cuda_runtime.h>
#include <cuda_bf16.h>
#include <cuda_fp16.h>
#include <cstdint>

// Problem constants (dataset-fixed): N=100000, E=1600000, F=128, H=4, C=32
#define NMAX 100000
#define EMAX 1600000

// Scratch (device globals — allocation-free per harness rules)
__device__ __align__(16) __half g_hf[(size_t)NMAX * 128];  // 25.6 MB, fp16 h
__device__ __align__(16) float g_asrc[(size_t)NMAX * 4];
__device__ __align__(16) float g_adst[(size_t)NMAX * 4];
__device__ __align__(16) __nv_bfloat16 g_wtb_hi[128 * 128];
__device__ __align__(16) __nv_bfloat16 g_wtb_lo[128 * 128];
__device__ int g_deg[NMAX + 1];
__device__ int g_off[NMAX + 1];
__device__ int g_cur[NMAX];
__device__ int g_csrc[EMAX];
__device__ int g_bsum[256];
__device__ int g_bpre[256];
__device__ int g_is64;

__device__ __forceinline__ float sel4(float4 v, int h) {
    float a = (h & 1) ? v.y : v.x;
    float b = (h & 1) ? v.w : v.z;
    return (h & 2) ? b : a;
}
__device__ __forceinline__ float lrelu(float v) { return v > 0.f ? v : 0.2f * v; }
__device__ __forceinline__ float bf16r(float x) {
    return __bfloat162float(__float2bfloat16(x));
}
__device__ __forceinline__ uint32_t pack_bf2(float lo, float hi) {
    uint32_t r;
    asm("cvt.rn.bf16x2.f32 %0, %1, %2;" : "=r"(r) : "f"(hi), "f"(lo));
    return r;
}
__device__ __forceinline__ void mma_bf16(float* c, uint32_t a0, uint32_t a1,
                                         uint32_t a2, uint32_t a3,
                                         uint32_t b0, uint32_t b1) {
    asm volatile(
        "mma.sync.aligned.m16n8k16.row.col.f32.bf16.bf16.f32 "
        "{%0,%1,%2,%3}, {%4,%5,%6,%7}, {%8,%9}, {%0,%1,%2,%3};"
        : "+f"(c[0]), "+f"(c[1]), "+f"(c[2]), "+f"(c[3])
        : "r"(a0), "r"(a1), "r"(a2), "r"(a3), "r"(b0), "r"(b1));
}
__device__ __forceinline__ void ldsm_x4(uint32_t* r, uint32_t saddr) {
    asm volatile(
        "ldmatrix.sync.aligned.m8n8.x4.shared.b16 {%0,%1,%2,%3}, [%4];"
        : "=r"(r[0]), "=r"(r[1]), "=r"(r[2]), "=r"(r[3]) : "r"(saddr));
}

// ---------------------------------------------------------------------------
__global__ void k_detect(const void* ei, int N) {
    const long long* p = (const long long*)ei;
    bool ok64 = true;
#pragma unroll
    for (int i = 0; i < 8; i++) {
        long long v = p[i];
        if (v < 0 || v >= N) ok64 = false;
    }
    g_is64 = ok64 ? 1 : 0;
}
__device__ __forceinline__ int edge_src(const void* ei, int e) {
    return g_is64 ? (int)__ldg((const long long*)ei + e) : __ldg((const int*)ei + e);
}
__device__ __forceinline__ int edge_dst(const void* ei, int e, int E) {
    return g_is64 ? (int)__ldg((const long long*)ei + (size_t)E + e)
                  : __ldg((const int*)ei + (size_t)E + e);
}

// ---------------------------------------------------------------------------
// CSR build
// ---------------------------------------------------------------------------
__global__ void k_zero(int N) {
    int i = blockIdx.x * blockDim.x + threadIdx.x;
    if (i <= N) g_deg[i] = 0;
}
__global__ void k_hist(const void* __restrict__ ei, int E) {
    int e = blockIdx.x * blockDim.x + threadIdx.x;
    if (e < E) atomicAdd(&g_deg[edge_dst(ei, e, E)], 1);
}
__global__ void __launch_bounds__(1024) k_scan1(int n) {
    __shared__ int warp_sums[32];
    const int tid = threadIdx.x, lane = tid & 31, wid = tid >> 5;
    int i = blockIdx.x * 1024 + tid;
    int v = (i < n) ? g_deg[i] : 0;
    int x = v;
#pragma unroll
    for (int off = 1; off < 32; off <<= 1) {
        int y = __shfl_up_sync(0xFFFFFFFFu, x, off);
        if (lane >= off) x += y;
    }
    if (lane == 31) warp_sums[wid] = x;
    __syncthreads();
    if (wid == 0) {
        int s = warp_sums[lane];
#pragma unroll
        for (int off = 1; off < 32; off <<= 1) {
            int y = __shfl_up_sync(0xFFFFFFFFu, s, off);
            if (lane >= off) s += y;
        }
        warp_sums[lane] = s;
    }
    __syncthreads();
    int incl = x + (wid ? warp_sums[wid - 1] : 0);
    if (i < n) g_off[i] = incl - v;
    if (tid == 1023) g_bsum[blockIdx.x] = incl;
}
__global__ void __launch_bounds__(256) k_scan2(int nb) {
    __shared__ int s[256];
    int tid = threadIdx.x;
    s[tid] = (tid < nb) ? g_bsum[tid] : 0;
    __syncthreads();
#pragma unroll
    for (int off = 1; off < 256; off <<= 1) {
        int v = (tid >= off) ? s[tid - off] : 0;
        __syncthreads();
        s[tid] += v;
        __syncthreads();
    }
    if (tid < nb) g_bpre[tid] = s[tid] - g_bsum[tid];
}
__global__ void __launch_bounds__(1024) k_scan3(int n, int E) {
    int i = blockIdx.x * 1024 + threadIdx.x;
    if (i < n) {
        int v = g_off[i] + g_bpre[blockIdx.x];
        g_off[i] = v;
        g_cur[i] = v;
    }
    if (i == n) g_off[n] = E;
}
__global__ void k_csr(const void* __restrict__ ei, int E) {
    int e = blockIdx.x * blockDim.x + threadIdx.x;
    if (e >= E) return;
    int s = edge_src(ei, e);
    int d = edge_dst(ei, e, E);
    int pos = atomicAdd(&g_cur[d], 1);
    g_csrc[pos] = s;
}

// ---------------------------------------------------------------------------
// W^T bf16 split precompute
// ---------------------------------------------------------------------------
__global__ void k_wt(const float* __restrict__ W) {
    int i = blockIdx.x * blockDim.x + threadIdx.x;
    if (i >= 128 * 128) return;
    int n = i >> 7, k = i & 127;
    float v = __ldg(W + k * 128 + n);
    float hi = bf16r(v);
    g_wtb_hi[i] = __float2bfloat16(v);
    g_wtb_lo[i] = __float2bfloat16(v - hi);
}

// ---------------------------------------------------------------------------
// GEMM via mma.sync m16n8k16 bf16, 3-term split + fused logits.
// v4: 128x128 CTA tile, 512 threads / 16 warps, ldmatrix fragments, and
// K-half software pipeline: prefetch half1 x into regs, MMA half0 covers
// the latency, then convert/store half1 and finish.
// ---------------------------------------------------------------------------
#define AS_STRIDE 136
#define SM_AHI 0
#define SM_ALO (128 * AS_STRIDE * 2)
#define SM_BHI (SM_ALO + 128 * AS_STRIDE * 2)
#define SM_BLO (SM_BHI + 128 * AS_STRIDE * 2)
#define SM_ATT (SM_BLO + 128 * AS_STRIDE * 2)
#define SM_TOT (SM_ATT + 1024)

__global__ void __launch_bounds__(512, 1)
k_gemm_mma(const float* __restrict__ x,
           const float* __restrict__ att_src, const float* __restrict__ att_dst,
           int N) {
    extern __shared__ char smem[];
    const int tid = threadIdx.x;
    const int row0 = blockIdx.x * 128;

    if (tid < 128)       *(float*)(smem + SM_ATT + tid * 4) = att_src[tid];
    else if (tid < 256)  *(float*)(smem + SM_ATT + 512 + (tid - 128) * 4) = att_dst[tid - 128];

    const float4* Xg = (const float4*)x;

    // A-load indexing per half: idx 0..2047, m = idx>>4, kf4 = (idx&15)+h*16
    int am[4], akf[4], agr[4];
#pragma unroll
    for (int i = 0; i < 4; i++) {
        int idx = tid + i * 512;
        am[i] = idx >> 4;
        akf[i] = idx & 15;
        agr[i] = row0 + am[i];
    }

    // ---- half 0: load + split + store
#pragma unroll
    for (int i = 0; i < 4; i++) {
        float4 v = (agr[i] < N) ? Xg[(size_t)agr[i] * 32 + akf[i]]
                                : make_float4(0.f, 0.f, 0.f, 0.f);
        float hx = bf16r(v.x), hy = bf16r(v.y), hz = bf16r(v.z), hw = bf16r(v.w);
        uint2 hi2 = make_uint2(pack_bf2(hx, hy), pack_bf2(hz, hw));
        uint2 lo2 = make_uint2(pack_bf2(v.x - hx, v.y - hy),
                               pack_bf2(v.z - hz, v.w - hw));
        uint32_t off = (uint32_t)(am[i] * AS_STRIDE + akf[i] * 4) * 2;
        *(uint2*)(smem + SM_AHI + off) = hi2;
        *(uint2*)(smem + SM_ALO + off) = lo2;
    }
    // ---- B (pre-split bf16 W^T): 128 n x 128 k
#pragma unroll
    for (int i = 0; i < 4; i++) {
        int idx = tid + i * 512;
        int n = idx >> 4, kb = (idx & 15) * 8;
        uint32_t off = (uint32_t)(n * AS_STRIDE + kb) * 2;
        *(uint4*)(smem + SM_BHI + off) = *(const uint4*)(g_wtb_hi + n * 128 + kb);
        *(uint4*)(smem + SM_BLO + off) = *(const uint4*)(g_wtb_lo + n * 128 + kb);
    }
    __syncthreads();

    // ---- prefetch half 1 x into registers (loads in flight during MMA half0)
    float4 pf[4];
#pragma unroll
    for (int i = 0; i < 4; i++) {
        pf[i] = (agr[i] < N) ? Xg[(size_t)agr[i] * 32 + 16 + akf[i]]
                             : make_float4(0.f, 0.f, 0.f, 0.f);
    }

    const int w = tid >> 5, lane = tid & 31;
    const int mw = w & 3, nw = w >> 2;
    const int m0 = mw * 32, n0 = nw * 32;
    const int g = lane >> 2, q = lane & 3;

    float acc[2][4][4];
#pragma unroll
    for (int a = 0; a < 2; a++)
#pragma unroll
        for (int b = 0; b < 4; b++)
#pragma unroll
            for (int c = 0; c < 4; c++) acc[a][b][c] = 0.f;

    const uint32_t sb = (uint32_t)__cvta_generic_to_shared(smem);
    uint32_t aHi[2], aLo[2], bHi[2], bLo[2];
    {
        int rl = ((lane >> 3) & 1) * 8 + (lane & 7);
        int kk = (lane >> 4) * 8;
#pragma unroll
        for (int ma = 0; ma < 2; ma++) {
            uint32_t off = (uint32_t)((m0 + ma * 16 + rl) * AS_STRIDE + kk) * 2;
            aHi[ma] = sb + SM_AHI + off;
            aLo[ma] = sb + SM_ALO + off;
        }
        int rlb = (lane >> 4) * 8 + (lane & 7);
        int kkb = ((lane >> 3) & 1) * 8;
#pragma unroll
        for (int p = 0; p < 2; p++) {
            uint32_t off = (uint32_t)((n0 + p * 16 + rlb) * AS_STRIDE + kkb) * 2;
            bHi[p] = sb + SM_BHI + off;
            bLo[p] = sb + SM_BLO + off;
        }
    }

    // ---- MMA half 0 (ka 0..3), overlapping the half-1 prefetch
#pragma unroll
    for (int ka = 0; ka < 4; ka++) {
        const uint32_t koff = ka * 32;
        uint32_t ah[2][4], al[2][4];
        uint32_t bh[4][2], bl[4][2];
#pragma unroll
        for (int ma = 0; ma < 2; ma++) {
            ldsm_x4(ah[ma], aHi[ma] + koff);
            ldsm_x4(al[ma], aLo[ma] + koff);
        }
#pragma unroll
        for (int p = 0; p < 2; p++) {
            ldsm_x4(&bh[2 * p][0], bHi[p] + koff);
            ldsm_x4(&bl[2 * p][0], bLo[p] + koff);
        }
#pragma unroll
        for (int ma = 0; ma < 2; ma++)
#pragma unroll
            for (int na = 0; na < 4; na++) {
                mma_bf16(acc[ma][na], ah[ma][0], ah[ma][1], ah[ma][2], ah[ma][3],
                         bh[na][0], bh[na][1]);
                mma_bf16(acc[ma][na], ah[ma][0], ah[ma][1], ah[ma][2], ah[ma][3],
                         bl[na][0], bl[na][1]);
                mma_bf16(acc[ma][na], al[ma][0], al[ma][1], al[ma][2], al[ma][3],
                         bh[na][0], bh[na][1]);
            }
    }

    // ---- convert + store half 1 (disjoint smem region), then sync
#pragma unroll
    for (int i = 0; i < 4; i++) {
        float4 v = pf[i];
        float hx = bf16r(v.x), hy = bf16r(v.y), hz = bf16r(v.z), hw = bf16r(v.w);
        uint2 hi2 = make_uint2(pack_bf2(hx, hy), pack_bf2(hz, hw));
        uint2 lo2 = make_uint2(pack_bf2(v.x - hx, v.y - hy),
                               pack_bf2(v.z - hz, v.w - hw));
        uint32_t off = (uint32_t)(am[i] * AS_STRIDE + (16 + akf[i]) * 4) * 2;
        *(uint2*)(smem + SM_AHI + off) = hi2;
        *(uint2*)(smem + SM_ALO + off) = lo2;
    }
    __syncthreads();

    // ---- MMA half 1 (ka 4..7)
#pragma unroll
    for (int ka = 4; ka < 8; ka++) {
        const uint32_t koff = ka * 32;
        uint32_t ah[2][4], al[2][4];
        uint32_t bh[4][2], bl[4][2];
#pragma unroll
        for (int ma = 0; ma < 2; ma++) {
            ldsm_x4(ah[ma], aHi[ma] + koff);
            ldsm_x4(al[ma], aLo[ma] + koff);
        }
#pragma unroll
        for (int p = 0; p < 2; p++) {
            ldsm_x4(&bh[2 * p][0], bHi[p] + koff);
            ldsm_x4(&bl[2 * p][0], bLo[p] + koff);
        }
#pragma unroll
        for (int ma = 0; ma < 2; ma++)
#pragma unroll
            for (int na = 0; na < 4; na++) {
                mma_bf16(acc[ma][na], ah[ma][0], ah[ma][1], ah[ma][2], ah[ma][3],
                         bh[na][0], bh[na][1]);
                mma_bf16(acc[ma][na], ah[ma][0], ah[ma][1], ah[ma][2], ah[ma][3],
                         bl[na][0], bl[na][1]);
                mma_bf16(acc[ma][na], al[ma][0], al[ma][1], al[ma][2], al[ma][3],
                         bh[na][0], bh[na][1]);
            }
    }

    // ---- epilogue: fp16 h rows + per-head logits (head = nw, warp-local)
    const float* s_as = (const float*)(smem + SM_ATT);
    const float* s_ad = (const float*)(smem + SM_ATT + 512);

#pragma unroll
    for (int ma = 0; ma < 2; ma++) {
#pragma unroll
        for (int half = 0; half < 2; half++) {
            int row = row0 + m0 + ma * 16 + g + half * 8;
            float as0 = 0.f, ad0 = 0.f;
#pragma unroll
            for (int na = 0; na < 4; na++) {
                int col = n0 + na * 8 + q * 2;
                float v0 = acc[ma][na][half * 2];
                float v1 = acc[ma][na][half * 2 + 1];
                if (row < N)
                    *(__half2*)(g_hf + (size_t)row * 128 + col) =
                        __floats2half2_rn(v0, v1);
                as0 += v0 * s_as[col] + v1 * s_as[col + 1];
                ad0 += v0 * s_ad[col] + v1 * s_ad[col + 1];
            }
#pragma unroll
            for (int off = 1; off < 4; off <<= 1) {
                as0 += __shfl_xor_sync(0xFFFFFFFFu, as0, off);
                ad0 += __shfl_xor_sync(0xFFFFFFFFu, ad0, off);
            }
            if (q == 0 && row < N) {
                g_asrc[(size_t)row * 4 + nw] = as0;
                g_adst[(size_t)row * 4 + nw] = ad0;
            }
        }
    }
}

// ---------------------------------------------------------------------------
// Aggregation v3 (proven best): Phase A parallel index+logit loads into smem,
// Phase B independent fp16 h-row gathers (uint2/lane). Zero atomics.
// ---------------------------------------------------------------------------
__global__ void __launch_bounds__(256) k_agg(float* __restrict__ out,
                                             const float* __restrict__ bias,
                                             int N) {
    __shared__ float p_sm[8][4][32];
    __shared__ int   s_sm[8][32];
    const int wib = threadIdx.x >> 5;
    const int d = (blockIdx.x * blockDim.x + threadIdx.x) >> 5;
    const int lane = threadIdx.x & 31;
    if (d >= N) return;
    const int hh = lane >> 3;

    const float4 ad4 = *(const float4*)(g_adst + (size_t)d * 4);
    const float adst_h = sel4(ad4, hh);
    const int beg = g_off[d];
    const int end = g_off[d + 1];

    float den = __expf(lrelu(__ldg(&g_asrc[(size_t)d * 4 + hh]) + adst_h));
    float4 acc;
    {
        uint2 u = __ldg((const uint2*)(g_hf + (size_t)d * 128) + lane);
        float2 f0 = __half22float2(*(__half2*)&u.x);
        float2 f1 = __half22float2(*(__half2*)&u.y);
        acc = make_float4(den * f0.x, den * f0.y, den * f1.x, den * f1.y);
    }

    for (int base = beg; base < end; base += 32) {
        const int cnt = min(32, end - base);
        {
            int j = base + lane;
            int s = d;
            float4 p4 = make_float4(0.f, 0.f, 0.f, 0.f);
            if (j < end) {
                s = __ldg(&g_csrc[j]);
                float4 a4 = *(const float4*)(g_asrc + (size_t)s * 4);
                p4.x = __expf(lrelu(a4.x + ad4.x));
                p4.y = __expf(lrelu(a4.y + ad4.y));
                p4.z = __expf(lrelu(a4.z + ad4.z));
                p4.w = __expf(lrelu(a4.w + ad4.w));
            }
            s_sm[wib][lane] = s;
            p_sm[wib][0][lane] = p4.x;
            p_sm[wib][1][lane] = p4.y;
            p_sm[wib][2][lane] = p4.z;
            p_sm[wib][3][lane] = p4.w;
        }
        __syncwarp();
#pragma unroll 4
        for (int t = 0; t < cnt; t++) {
            int ss = s_sm[wib][t];
            float p = p_sm[wib][hh][t];
            den += p;
            uint2 u = __ldg((const uint2*)(g_hf + (size_t)ss * 128) + lane);
            float2 f0 = __half22float2(*(__half2*)&u.x);
            float2 f1 = __half22float2(*(__half2*)&u.y);
            acc.x = fmaf(p, f0.x, acc.x);
            acc.y = fmaf(p, f0.y, acc.y);
            acc.z = fmaf(p, f1.x, acc.z);
            acc.w = fmaf(p, f1.y, acc.w);
        }
        __syncwarp();
    }

    const float inv = __fdividef(1.0f, den);
    float4 b4 = ((const float4*)bias)[lane];
    acc.x = fmaf(acc.x, inv, b4.x);
    acc.y = fmaf(acc.y, inv, b4.y);
    acc.z = fmaf(acc.z, inv, b4.z);
    acc.w = fmaf(acc.w, inv, b4.w);
    ((float4*)(out + (size_t)d * 128))[lane] = acc;
}

// ---------------------------------------------------------------------------
extern "C" void kernel_launch(void* const* d_in, const int* in_sizes, int n_in,
                              void* d_out, int out_size) {
    int idx_W = -1;
    int small[3] = {-1, -1, -1}; int ns = 0;
    for (int i = 0; i < n_in; i++) {
        int sz = in_sizes[i];
        if (sz == 128 && ns < 3)  small[ns++] = i;
        else if (sz == 128 * 128) idx_W = i;
    }
    int idx_x = -1, idx_e = -1;
    for (int i = 0; i < n_in; i++) {
        if (in_sizes[i] == 128 || in_sizes[i] == 128 * 128) continue;
        if (idx_x < 0 || in_sizes[i] > in_sizes[idx_x]) { idx_e = idx_x; idx_x = i; }
        else if (idx_e < 0 || in_sizes[i] > in_sizes[idx_e]) { idx_e = i; }
    }
    int idx_asrc, idx_adst, idx_bias;
    if (idx_x < small[0]) { idx_asrc = small[0]; idx_adst = small[1]; idx_bias = small[2]; }
    else                  { idx_adst = small[0]; idx_asrc = small[1]; idx_bias = small[2]; }

    const float* x       = (const float*)d_in[idx_x];
    const void*  ei      = d_in[idx_e];
    const float* W       = (const float*)d_in[idx_W];
    const float* att_src = (const float*)d_in[idx_asrc];
    const float* att_dst = (const float*)d_in[idx_adst];
    const float* bias    = (const float*)d_in[idx_bias];
    float* out           = (float*)d_out;

    const int N = in_sizes[idx_x] / 128;
    const int E = in_sizes[idx_e] / 2;
    const int nb = (N + 1023) / 1024;

    static cudaStream_t s2 = nullptr;
    static cudaEvent_t evFork = nullptr, evJoin = nullptr;
    if (!s2) {
        cudaFuncSetAttribute(k_gemm_mma, cudaFuncAttributeMaxDynamicSharedMemorySize, SM_TOT);
        cudaStreamCreateWithFlags(&s2, cudaStreamNonBlocking);
        cudaEventCreateWithFlags(&evFork, cudaEventDisableTiming);
        cudaEventCreateWithFlags(&evJoin, cudaEventDisableTiming);
    }

    cudaEventRecord(evFork, 0);
    cudaStreamWaitEvent(s2, evFork, 0);

    // Submission order: index 3 = k_gemm_mma (ncu profiles 4th launch).
    k_detect<<<1, 1, 0, s2>>>(ei, N);                            // 0
    k_wt<<<(128 * 128 + 255) / 256, 256>>>(W);                   // 1 (default)
    k_zero<<<(N + 256) / 256, 256, 0, s2>>>(N);                  // 2
    k_gemm_mma<<<(N + 127) / 128, 512, SM_TOT>>>(x, att_src, att_dst, N); // 3 (default)
    k_hist<<<(E + 255) / 256, 256, 0, s2>>>(ei, E);              // 4
    k_scan1<<<nb, 1024, 0, s2>>>(N);
    k_scan2<<<1, 256, 0, s2>>>(nb);
    k_scan3<<<nb + 1, 1024, 0, s2>>>(N, E);
    k_csr<<<(E + 255) / 256, 256, 0, s2>>>(ei, E);

    cudaEventRecord(evJoin, s2);
    cudaStreamWaitEvent(0, evJoin, 0);
    {
        long long threads = (long long)N * 32;
        int blocks = (int)((threads + 255) / 256);
        k_agg<<<blocks, 256>>>(out, bias, N);
    }
}